// round 15
// baseline (speedup 1.0000x reference)
#include <cuda_runtime.h>
#include <cuda_fp16.h>
#include <cstdint>

#define BATCH 128
#define NH    8
#define NT    256
#define HDIM  64
#define MODEL 512
#define NBH   (BATCH*NH)    // 1024
#define MTOT  (BATCH*NT)    // 32768
#define QKVN  (3*NH*HDIM)   // 1536

// ---------------- scratch (static __device__, no runtime allocation) -------
__device__ float  g_v[(size_t)NBH*NT*HDIM];          // V fp32
__device__ float  g_S[(size_t)NBH*NT*NT];            // scores fp32
__device__ __half g_xh[(size_t)MTOT*MODEL];          // x rounded fp16
__device__ __half g_qwse[(size_t)QKVN*1024];         // [Wh|Wl] qkv_w
__device__ __half g_pwse[(size_t)MODEL*1024];        // [Wh|Wl] proj_w
__device__ __half g_qh[(size_t)NBH*NT*HDIM];         // q fp16 (scaled)
__device__ __half g_kes[(size_t)NBH*NT*128];         // [kh|kl]
__device__ __half g_ph[(size_t)NBH*NT*NT];           // P fp16
__device__ __half g_vte[(size_t)NBH*64*512];         // [Vh|Vl] transposed
__device__ __half g_oh16[(size_t)MTOT*MODEL];        // attn out fp16

// ---------------- helpers ---------------------------------------------------
__device__ __forceinline__ uint32_t smem_u32(const void* p) {
    uint32_t a;
    asm("{ .reg .u64 t; cvta.to.shared.u64 t, %1; cvt.u32.u64 %0, t; }"
        : "=r"(a) : "l"(p));
    return a;
}
__device__ __forceinline__ void cp16(uint32_t s, const void* g) {
    asm volatile("cp.async.cg.shared.global [%0], [%1], 16;" :: "r"(s), "l"(g));
}
#define CP_COMMIT() asm volatile("cp.async.commit_group;")
#define CP_WAIT0()  asm volatile("cp.async.wait_group 0;")
#define CP_WAIT1()  asm volatile("cp.async.wait_group 1;")
__device__ __forceinline__ void ldm4(uint32_t& r0, uint32_t& r1, uint32_t& r2,
                                     uint32_t& r3, uint32_t a) {
    asm volatile("ldmatrix.sync.aligned.m8n8.x4.shared.b16 {%0,%1,%2,%3}, [%4];"
                 : "=r"(r0), "=r"(r1), "=r"(r2), "=r"(r3) : "r"(a));
}
__device__ __forceinline__ void mma16816h(float* c, const uint32_t* a,
                                          uint32_t b0, uint32_t b1) {
    asm volatile(
        "mma.sync.aligned.m16n8k16.row.col.f32.f16.f16.f32 "
        "{%0,%1,%2,%3}, {%4,%5,%6,%7}, {%8,%9}, {%0,%1,%2,%3};"
        : "+f"(c[0]), "+f"(c[1]), "+f"(c[2]), "+f"(c[3])
        : "r"(a[0]), "r"(a[1]), "r"(a[2]), "r"(a[3]), "r"(b0), "r"(b1));
}
__device__ __forceinline__ void split1h(float v, __half& h, __half& l) {
    h = __float2half_rn(v);
    l = __float2half_rn(v - __half2float(h));
}

// ---------------- prep kernels ----------------------------------------------
// round x to fp16 (vectorized x2)
__global__ void rnd_x_kernel(const float* __restrict__ s, __half* d, int totpairs) {
    int i = blockIdx.x * 256 + threadIdx.x;
    if (i >= totpairs) return;
    float2 v = ((const float2*)s)[i];
    __half2 t; t.x = __float2half_rn(v.x); t.y = __float2half_rn(v.y);
    ((__half2*)d)[i] = t;
}
// weight split: row K=512 -> [Wh(512) | Wl(512)]
__global__ void wsplit_kernel(const float* __restrict__ s, __half* d, int totpairs) {
    int i = blockIdx.x * 256 + threadIdx.x;
    if (i >= totpairs) return;
    int r = i >> 8, kp = i & 255;
    float2 v = ((const float2*)s)[i];
    __half h0, l0, h1, l1;
    split1h(v.x, h0, l0); split1h(v.y, h1, l1);
    __half2 th, tl; th.x = h0; th.y = h1; tl.x = l0; tl.y = l1;
    __half2* base = (__half2*)(d + (size_t)r * 1024) + kp;
    base[0] = th; base[256] = tl;
}

// ---------------- fp16 2-term GEMM ------------------------------------------
// C[M,N] = A[M,512](fp16) @ B_ext[N,1024]([Bh|Bl])^T (+bias)
// BM=128 BN=128 BK=32, 3 stages, 2 CTAs/SM.
#define BM 128
#define BN 128
#define BK 32
#define NSTG 3
#define GAROW 80u                          // 32 fp16 = 64B + 16 pad
#define GA_SZ (128u * GAROW)               // 10240
#define STGB  (3u * GA_SZ)                 // A + Bh + Bl = 30720
#define GSMEM (NSTG * STGB)                // 92160

template<int MODE>
__global__ __launch_bounds__(256, 2) void gemm_mma(
    const __half* __restrict__ gA, const __half* __restrict__ gB,
    const float* __restrict__ bias, float* __restrict__ outp)
{
    extern __shared__ char smem[];
    const uint32_t sb = smem_u32(smem);
    const int tid = threadIdx.x, wid = tid >> 5, lane = tid & 31;
    const int m0 = blockIdx.y * BM;
    const int n0 = blockIdx.x * BN;
    const int warp_m = (wid & 3) * 32;
    const int warp_n = (wid >> 2) * 64;

    auto load_stage = [&](int ks, int buf) {
        const int kofs = ks * BK;
        const uint32_t abase = sb + buf * STGB;
        #pragma unroll
        for (int t = 0; t < 6; t++) {
            const int idx = tid + t * 256;
            if (idx < 512) {                   // A: 128 rows x 4 chunks
                const int r = idx >> 2, c = (idx & 3) * 8;
                cp16(abase + r * GAROW + c * 2,
                     gA + (size_t)(m0 + r) * 512 + kofs + c);
            } else if (idx < 1024) {           // Bh
                const int j = idx - 512;
                const int r = j >> 2, c = (j & 3) * 8;
                cp16(abase + GA_SZ + r * GAROW + c * 2,
                     gB + (size_t)(n0 + r) * 1024 + kofs + c);
            } else {                           // Bl
                const int j = idx - 1024;
                const int r = j >> 2, c = (j & 3) * 8;
                cp16(abase + 2 * GA_SZ + r * GAROW + c * 2,
                     gB + (size_t)(n0 + r) * 1024 + 512 + kofs + c);
            }
        }
    };

    const int NK = 512 / BK;   // 16
    load_stage(0, 0); CP_COMMIT();
    load_stage(1, 1); CP_COMMIT();

    float acc[2][8][4] = {};
    const int a_row = warp_m + (lane & 15);
    const int a_col = (lane >> 4) * 8;
    const int b_row = warp_n + (lane & 7) + ((lane >> 4) << 3);
    const int b_col = ((lane >> 3) & 1) * 8;

    for (int ks = 0; ks < NK; ks++) {
        CP_WAIT1();
        __syncthreads();
        const int pf = ks + NSTG - 1;
        if (pf < NK) load_stage(pf, pf % NSTG);
        CP_COMMIT();
        const uint32_t abase = sb + (ks % NSTG) * STGB;
        #pragma unroll
        for (int kk = 0; kk < 2; kk++) {
            uint32_t af[2][4];
            #pragma unroll
            for (int im = 0; im < 2; im++)
                ldm4(af[im][0], af[im][1], af[im][2], af[im][3],
                     abase + (a_row + im * 16) * GAROW + (kk * 16 + a_col) * 2);
            #pragma unroll
            for (int hv = 0; hv < 2; hv++) {
                const uint32_t bbase = abase + (1 + hv) * GA_SZ;
                uint32_t bfr[4][4];
                #pragma unroll
                for (int jn = 0; jn < 4; jn++)
                    ldm4(bfr[jn][0], bfr[jn][1], bfr[jn][2], bfr[jn][3],
                         bbase + (b_row + jn * 16) * GAROW + (kk * 16 + b_col) * 2);
                #pragma unroll
                for (int jn = 0; jn < 4; jn++)
                    #pragma unroll
                    for (int im = 0; im < 2; im++) {
                        mma16816h(acc[im][jn * 2 + 0], af[im], bfr[jn][0], bfr[jn][1]);
                        mma16816h(acc[im][jn * 2 + 1], af[im], bfr[jn][2], bfr[jn][3]);
                    }
            }
        }
    }

    const int mb = m0 + warp_m + (lane >> 2);
    #pragma unroll
    for (int im = 0; im < 2; im++) {
        #pragma unroll
        for (int j = 0; j < 8; j++) {
            const int col = n0 + warp_n + j * 8 + (lane & 3) * 2;
            #pragma unroll
            for (int half = 0; half < 2; half++) {
                const int m = mb + im * 16 + half * 8;
                float v0 = acc[im][j][half * 2 + 0] + bias[col];
                float v1 = acc[im][j][half * 2 + 1] + bias[col + 1];
                if (MODE == 0) {
                    const int sct = col >> 9, h = (col >> 6) & 7, d = col & 63;
                    const int bi = m >> 8, nt = m & 255;
                    if (sct == 2) {
                        float2* dp = (float2*)(g_v +
                            (((size_t)(bi * NH + h) * NT + nt) * HDIM + d));
                        *dp = make_float2(v0, v1);
                    } else if (sct == 0) {
                        v0 *= 0.125f; v1 *= 0.125f;
                        __half2 t; t.x = __float2half_rn(v0); t.y = __float2half_rn(v1);
                        *(__half2*)(g_qh + ((size_t)(bi * NH + h) * NT + nt) * 64 + d) = t;
                    } else {
                        __half h0, l0, h1, l1;
                        split1h(v0, h0, l0); split1h(v1, h1, l1);
                        __half* base = g_kes + ((size_t)(bi * NH + h) * NT + nt) * 128 + d;
                        __half2 th, tl; th.x = h0; th.y = h1; tl.x = l0; tl.y = l1;
                        *(__half2*)(base)      = th;
                        *(__half2*)(base + 64) = tl;
                    }
                } else {
                    *(float2*)(outp + (size_t)m * MODEL + col) = make_float2(v0, v1);
                }
            }
        }
    }
}

// ---------------- s_mma: S = q(fp16) @ k_ext^T, load-once, 2 terms ----------
#define SAROW 144u                        // 64 fp16 = 128B + 16 pad
#define SBROW 272u                        // 128 fp16 = 256B + 16 pad
#define SSMEM (128u * SAROW + 128u * SBROW)   // 53248

__global__ __launch_bounds__(256, 2) void s_mma()
{
    extern __shared__ char smem[];
    const uint32_t sb = smem_u32(smem);
    const int tid = threadIdx.x, wid = tid >> 5, lane = tid & 31;
    const int bh = blockIdx.y;
    const int m0 = (blockIdx.x >> 1) * 128;
    const int n0 = (blockIdx.x & 1) * 128;
    const __half* gA = g_qh  + (size_t)bh * NT * 64;
    const __half* gB = g_kes + (size_t)bh * NT * 128;
    const int warp_m = (wid & 3) * 32;
    const int warp_n = (wid >> 2) * 64;
    const uint32_t abase = sb;
    const uint32_t bbase = sb + 128u * SAROW;

    #pragma unroll
    for (int t = 0; t < 12; t++) {
        const int idx = tid + t * 256;
        if (idx < 1024) {           // A: 128 rows x 8 chunks
            const int r = idx >> 3, c = (idx & 7) * 8;
            cp16(abase + r * SAROW + c * 2, gA + (size_t)(m0 + r) * 64 + c);
        } else {                    // B: 128 rows x 16 chunks
            const int j = idx - 1024;
            const int r = j >> 4, cc = j & 15;
            cp16(bbase + r * SBROW + cc * 16, gB + (size_t)(n0 + r) * 128 + cc * 8);
        }
    }
    CP_COMMIT();
    CP_WAIT0();
    __syncthreads();

    float acc[2][8][4] = {};
    const int a_row = warp_m + (lane & 15);
    const int a_col = (lane >> 4) * 8;
    const int b_row = warp_n + (lane & 7) + ((lane >> 4) << 3);
    const int b_col = ((lane >> 3) & 1) * 8;

    #pragma unroll
    for (int kk = 0; kk < 4; kk++) {
        uint32_t af[2][4];
        #pragma unroll
        for (int im = 0; im < 2; im++)
            ldm4(af[im][0], af[im][1], af[im][2], af[im][3],
                 abase + (a_row + im * 16) * SAROW + (kk * 16 + a_col) * 2);
        #pragma unroll
        for (int term = 0; term < 2; term++) {
            const int bo = term * 64;
            uint32_t bfr[4][4];
            #pragma unroll
            for (int jn = 0; jn < 4; jn++)
                ldm4(bfr[jn][0], bfr[jn][1], bfr[jn][2], bfr[jn][3],
                     bbase + (b_row + jn * 16) * SBROW + (bo + kk * 16 + b_col) * 2);
            #pragma unroll
            for (int jn = 0; jn < 4; jn++)
                #pragma unroll
                for (int im = 0; im < 2; im++) {
                    mma16816h(acc[im][jn * 2 + 0], af[im], bfr[jn][0], bfr[jn][1]);
                    mma16816h(acc[im][jn * 2 + 1], af[im], bfr[jn][2], bfr[jn][3]);
                }
        }
    }

    float* Sp = g_S + (size_t)bh * NT * NT;
    const int mb = m0 + warp_m + (lane >> 2);
    #pragma unroll
    for (int im = 0; im < 2; im++) {
        #pragma unroll
        for (int j = 0; j < 8; j++) {
            const int col = n0 + warp_n + j * 8 + (lane & 3) * 2;
            #pragma unroll
            for (int half = 0; half < 2; half++) {
                const int m = mb + im * 16 + half * 8;
                *(float2*)(Sp + (size_t)m * NT + col) =
                    make_float2(acc[im][j][half * 2], acc[im][j][half * 2 + 1]);
            }
        }
    }
}

// ---------------- vt_kernel: transpose + fp16 split V -----------------------
__global__ __launch_bounds__(256) void vt_kernel()
{
    __shared__ float sv[128 * 65];
    const int bh = blockIdx.x, tid = threadIdx.x;
    const float* V = g_v + (size_t)bh * NT * HDIM;
    __half* dst = g_vte + (size_t)bh * 64 * 512;
    for (int pass = 0; pass < 2; pass++) {
        const int kbase = pass * 128;
        for (int i = tid; i < 128 * 64; i += 256) {
            int k2 = i >> 6, n = i & 63;
            sv[k2 * 65 + n] = V[(size_t)(kbase + k2) * 64 + n];
        }
        __syncthreads();
        const int n = tid >> 2, q = tid & 3;
        for (int kk = 0; kk < 32; kk += 2) {
            const int k2 = q * 32 + kk;
            float v0 = sv[k2 * 65 + n], v1 = sv[(k2 + 1) * 65 + n];
            __half h0, l0, h1, l1;
            split1h(v0, h0, l0); split1h(v1, h1, l1);
            __half2 th, tl; th.x = h0; th.y = h1; tl.x = l0; tl.y = l1;
            const int k = kbase + k2;
            *(__half2*)(dst + (size_t)n * 512 + k)       = th;
            *(__half2*)(dst + (size_t)n * 512 + 256 + k) = tl;
        }
        __syncthreads();
    }
}

// ---------------- conv + bias + softmax -> P fp16 ---------------------------
__global__ __launch_bounds__(256) void conv_softmax_kernel(
    const float* __restrict__ pe_w, const float* __restrict__ pe_b,
    const float* __restrict__ rpb)
{
    __shared__ float st[32][NT];
    const int bh = blockIdx.y;
    const int h  = bh & 7;
    const int i0 = blockIdx.x * 32;
    const float* S = g_S + (size_t)bh * NT * NT;
    __half* pe = g_ph + (size_t)bh * NT * NT;
    const int j = threadIdx.x;

    float win[46];
    #pragma unroll
    for (int r = 0; r < 46; r++) {
        const int g = i0 - 7 + r;
        win[r] = (g >= 0 && g < NT) ? S[(size_t)g * NT + j] : 0.f;
    }
    float w[15];
    #pragma unroll
    for (int t = 0; t < 15; t++) w[t] = pe_w[h * 15 + t];
    const float pb = pe_b[h];
    const int rj = j >> 4, cj = j & 15;

    #pragma unroll
    for (int li = 0; li < 32; li++) {
        float conv = 0.f;
        #pragma unroll
        for (int t = 0; t < 15; t++)
            conv = fmaf(win[li + t], w[t], conv);
        const int ii = i0 + li;
        const int ri = ii >> 4, ci = ii & 15;
        const int idx = (ri - rj + 15) * 31 + (ci - cj + 15);
        st[li][j] = win[li + 7] + conv + pb + __ldg(&rpb[idx * 8 + h]);
    }
    __syncthreads();

    const int warp = j >> 5, lane = j & 31;
    #pragma unroll
    for (int rr = 0; rr < 4; rr++) {
        const int li = warp * 4 + rr;
        const int ii = i0 + li;
        float vals[8];
        #pragma unroll
        for (int e = 0; e < 8; e++) vals[e] = st[li][lane + e * 32];
        float mx = vals[0];
        #pragma unroll
        for (int e = 1; e < 8; e++) mx = fmaxf(mx, vals[e]);
        #pragma unroll
        for (int o = 16; o; o >>= 1) mx = fmaxf(mx, __shfl_xor_sync(0xffffffffu, mx, o));
        float sum = 0.f;
        #pragma unroll
        for (int e = 0; e < 8; e++) { vals[e] = __expf(vals[e] - mx); sum += vals[e]; }
        #pragma unroll
        for (int o = 16; o; o >>= 1) sum += __shfl_xor_sync(0xffffffffu, sum, o);
        const float inv = 1.f / sum;
        #pragma unroll
        for (int e = 0; e < 8; e++)
            pe[(size_t)ii * NT + lane + e * 32] = __float2half_rn(vals[e] * inv);
    }
}

// ---------------- av_mma: O = P(fp16) @ V_ext^T, 2 terms --------------------
#define AVROW 80u
#define AV_A  0u
#define AV_BH (256u * AVROW)              // 20480
#define AV_BL (AV_BH + 64u * AVROW)       // 25600
#define AV_STG (AV_BL + 64u * AVROW)      // 30720
#define AVSMEM (2u * AV_STG)              // 61440

__global__ __launch_bounds__(256, 2) void av_mma()
{
    extern __shared__ char smem[];
    const uint32_t sb = smem_u32(smem);
    const int tid = threadIdx.x, wid = tid >> 5, lane = tid & 31;
    const int bh = blockIdx.x;
    const __half* gA = g_ph  + (size_t)bh * NT * NT;
    const __half* gB = g_vte + (size_t)bh * 64 * 512;
    const int warp_m = (wid & 3) * 64;
    const int warp_n = (wid >> 2) * 32;

    auto load_stage = [&](int c, int buf) {
        const uint32_t base = sb + buf * AV_STG;
        #pragma unroll
        for (int t = 0; t < 6; t++) {
            const int idx = tid + t * 256;
            if (idx < 1024) {                     // P: 256 rows x 4 chunks
                const int r = idx >> 2, col = (idx & 3) * 8;
                cp16(base + AV_A + r * AVROW + col * 2,
                     gA + (size_t)r * 256 + c * 32 + col);
            } else if (idx < 1280) {              // Vh: 64 rows x 4 chunks
                const int i2 = idx - 1024;
                const int r = i2 >> 2, col = (i2 & 3) * 8;
                cp16(base + AV_BH + r * AVROW + col * 2,
                     gB + (size_t)r * 512 + c * 32 + col);
            } else {                              // Vl
                const int i3 = idx - 1280;
                const int r = i3 >> 2, col = (i3 & 3) * 8;
                cp16(base + AV_BL + r * AVROW + col * 2,
                     gB + (size_t)r * 512 + 256 + c * 32 + col);
            }
        }
    };

    load_stage(0, 0); CP_COMMIT();

    float acc[4][4][4] = {};
    const int a_row = warp_m + (lane & 15);
    const int a_col = (lane >> 4) * 8;
    const int b_row = warp_n + (lane & 7) + ((lane >> 4) << 3);
    const int b_col = ((lane >> 3) & 1) * 8;

    for (int ks = 0; ks < 8; ks++) {
        if (ks > 0) __syncthreads();
        if (ks + 1 < 8) load_stage(ks + 1, (ks + 1) & 1);
        CP_COMMIT();
        if (ks < 7) CP_WAIT1(); else CP_WAIT0();
        __syncthreads();
        const uint32_t base = sb + (ks & 1) * AV_STG;
        #pragma unroll
        for (int kk = 0; kk < 2; kk++) {
            uint32_t af[4][4];
            #pragma unroll
            for (int im = 0; im < 4; im++)
                ldm4(af[im][0], af[im][1], af[im][2], af[im][3],
                     base + AV_A + (a_row + im * 16) * AVROW + (kk * 16 + a_col) * 2);
            #pragma unroll
            for (int hv = 0; hv < 2; hv++) {
                const uint32_t bbase = base + (hv ? AV_BL : AV_BH);
                uint32_t bfr[2][4];
                #pragma unroll
                for (int jn = 0; jn < 2; jn++)
                    ldm4(bfr[jn][0], bfr[jn][1], bfr[jn][2], bfr[jn][3],
                         bbase + (b_row + jn * 16) * AVROW + (kk * 16 + b_col) * 2);
                #pragma unroll
                for (int jn = 0; jn < 2; jn++)
                    #pragma unroll
                    for (int im = 0; im < 4; im++) {
                        mma16816h(acc[im][jn * 2 + 0], af[im], bfr[jn][0], bfr[jn][1]);
                        mma16816h(acc[im][jn * 2 + 1], af[im], bfr[jn][2], bfr[jn][3]);
                    }
            }
        }
    }

    const int bi = bh >> 3, hh = bh & 7;
    #pragma unroll
    for (int im = 0; im < 4; im++) {
        #pragma unroll
        for (int j = 0; j < 4; j++) {
            const int col = warp_n + j * 8 + (lane & 3) * 2;   // 0..63
            #pragma unroll
            for (int half = 0; half < 2; half++) {
                const int m = warp_m + im * 16 + (lane >> 2) + half * 8;
                __half2 t;
                t.x = __float2half_rn(acc[im][j][half * 2 + 0]);
                t.y = __float2half_rn(acc[im][j][half * 2 + 1]);
                *(__half2*)(g_oh16 + (size_t)(bi * NT + m) * MODEL + hh * 64 + col) = t;
            }
        }
    }
}

// ---------------------------------------------------------------------------
extern "C" void kernel_launch(void* const* d_in, const int* in_sizes, int n_in,
                              void* d_out, int out_size)
{
    (void)in_sizes; (void)n_in; (void)out_size;
    const float* x      = (const float*)d_in[0];
    const float* qkv_w  = (const float*)d_in[1];
    const float* qkv_b  = (const float*)d_in[2];
    const float* pe_w   = (const float*)d_in[3];
    const float* pe_b   = (const float*)d_in[4];
    const float* rpb    = (const float*)d_in[5];
    const float* proj_w = (const float*)d_in[6];
    const float* proj_b = (const float*)d_in[7];
    float* out = (float*)d_out;

    static bool attr_done = false;
    if (!attr_done) {
        cudaFuncSetAttribute(gemm_mma<0>, cudaFuncAttributeMaxDynamicSharedMemorySize, GSMEM);
        cudaFuncSetAttribute(gemm_mma<1>, cudaFuncAttributeMaxDynamicSharedMemorySize, GSMEM);
        cudaFuncSetAttribute(s_mma, cudaFuncAttributeMaxDynamicSharedMemorySize, SSMEM);
        cudaFuncSetAttribute(av_mma, cudaFuncAttributeMaxDynamicSharedMemorySize, AVSMEM);
        attr_done = true;
    }

    __half *xh, *qws, *pws, *oh16;
    cudaGetSymbolAddress((void**)&xh,   g_xh);
    cudaGetSymbolAddress((void**)&qws,  g_qwse);
    cudaGetSymbolAddress((void**)&pws,  g_pwse);
    cudaGetSymbolAddress((void**)&oh16, g_oh16);

    rnd_x_kernel<<<(MTOT * MODEL / 2 + 255) / 256, 256>>>(x, xh, MTOT * MODEL / 2);
    wsplit_kernel<<<(QKVN * MODEL / 2 + 255) / 256, 256>>>(qkv_w, qws, QKVN * MODEL / 2);
    wsplit_kernel<<<(MODEL * MODEL / 2 + 255) / 256, 256>>>(proj_w, pws, MODEL * MODEL / 2);

    gemm_mma<0><<<dim3(QKVN / BN, MTOT / BM), 256, GSMEM>>>(xh, qws, qkv_b, nullptr);

    vt_kernel<<<NBH, 256>>>();
    s_mma<<<dim3(4, NBH), 256, SSMEM>>>();
    conv_softmax_kernel<<<dim3(8, NBH), 256>>>(pe_w, pe_b, rpb);
    av_mma<<<NBH, 256, AVSMEM>>>();

    gemm_mma<1><<<dim3(MODEL / BN, MTOT / BM), 256, GSMEM>>>(oh16, pws, proj_b, out);
}

// round 16
// speedup vs baseline: 1.5396x; 1.5396x over previous
#include <cuda_runtime.h>
#include <cuda_fp16.h>
#include <cstdint>

#define BATCH 128
#define NH    8
#define NT    256
#define HDIM  64
#define MODEL 512
#define NBH   (BATCH*NH)    // 1024
#define MTOT  (BATCH*NT)    // 32768
#define QKVN  (3*NH*HDIM)   // 1536

// ---------------- scratch (static __device__, no runtime allocation) -------
__device__ float  g_v[(size_t)NBH*NT*HDIM];          // V fp32
__device__ float  g_S[(size_t)NBH*NT*NT];            // scores fp32
__device__ __half g_xh[(size_t)MTOT*MODEL];          // x rounded fp16
__device__ __half g_qwse[(size_t)QKVN*1024];         // [Wh|Wl] qkv_w
__device__ __half g_pwse[(size_t)MODEL*1024];        // [Wh|Wl] proj_w
__device__ __half g_qh[(size_t)NBH*NT*HDIM];         // q fp16 (scaled)
__device__ __half g_kes[(size_t)NBH*NT*128];         // [kh|kl]
__device__ __half g_ph[(size_t)NBH*NT*NT];           // P fp16
__device__ __half g_vte[(size_t)NBH*64*512];         // [Vh|Vl] transposed
__device__ __half g_oh16[(size_t)MTOT*MODEL];        // attn out fp16

// ---------------- helpers ---------------------------------------------------
__device__ __forceinline__ uint32_t smem_u32(const void* p) {
    uint32_t a;
    asm("{ .reg .u64 t; cvta.to.shared.u64 t, %1; cvt.u32.u64 %0, t; }"
        : "=r"(a) : "l"(p));
    return a;
}
__device__ __forceinline__ void cp16(uint32_t s, const void* g) {
    asm volatile("cp.async.cg.shared.global [%0], [%1], 16;" :: "r"(s), "l"(g));
}
#define CP_COMMIT() asm volatile("cp.async.commit_group;")
#define CP_WAIT0()  asm volatile("cp.async.wait_group 0;")
#define CP_WAIT1()  asm volatile("cp.async.wait_group 1;")
__device__ __forceinline__ void ldm4(uint32_t& r0, uint32_t& r1, uint32_t& r2,
                                     uint32_t& r3, uint32_t a) {
    asm volatile("ldmatrix.sync.aligned.m8n8.x4.shared.b16 {%0,%1,%2,%3}, [%4];"
                 : "=r"(r0), "=r"(r1), "=r"(r2), "=r"(r3) : "r"(a));
}
__device__ __forceinline__ void mma16816h(float* c, const uint32_t* a,
                                          uint32_t b0, uint32_t b1) {
    asm volatile(
        "mma.sync.aligned.m16n8k16.row.col.f32.f16.f16.f32 "
        "{%0,%1,%2,%3}, {%4,%5,%6,%7}, {%8,%9}, {%0,%1,%2,%3};"
        : "+f"(c[0]), "+f"(c[1]), "+f"(c[2]), "+f"(c[3])
        : "r"(a[0]), "r"(a[1]), "r"(a[2]), "r"(a[3]), "r"(b0), "r"(b1));
}
__device__ __forceinline__ void split1h(float v, __half& h, __half& l) {
    h = __float2half_rn(v);
    l = __float2half_rn(v - __half2float(h));
}

// ---------------- prep kernels ----------------------------------------------
__global__ void rnd_x_kernel(const float* __restrict__ s, __half* d, int totpairs) {
    int i = blockIdx.x * 256 + threadIdx.x;
    if (i >= totpairs) return;
    float2 v = ((const float2*)s)[i];
    __half2 t; t.x = __float2half_rn(v.x); t.y = __float2half_rn(v.y);
    ((__half2*)d)[i] = t;
}
__global__ void wsplit_kernel(const float* __restrict__ s, __half* d, int totpairs) {
    int i = blockIdx.x * 256 + threadIdx.x;
    if (i >= totpairs) return;
    int r = i >> 8, kp = i & 255;
    float2 v = ((const float2*)s)[i];
    __half h0, l0, h1, l1;
    split1h(v.x, h0, l0); split1h(v.y, h1, l1);
    __half2 th, tl; th.x = h0; th.y = h1; tl.x = l0; tl.y = l1;
    __half2* base = (__half2*)(d + (size_t)r * 1024) + kp;
    base[0] = th; base[256] = tl;
}

// ---------------- fp16 2-term GEMM, term-mapped BK=64 stages ----------------
// ext K = 1024: stage ks<8 -> (A[ks], Bh[ks]); ks>=8 -> (A[ks-8], Bl[ks-8]).
#define BM 128
#define BN 128
#define NSTG 3
#define ROWB 144u                         // 64 fp16 = 128B + 16 pad
#define STGB (2u * 128u * ROWB)           // 36864
#define GSMEM (NSTG * STGB)               // 110592

template<int MODE>
__global__ __launch_bounds__(256, 2) void gemm_mma(
    const __half* __restrict__ gA, const __half* __restrict__ gB,
    const float* __restrict__ bias, float* __restrict__ outp)
{
    extern __shared__ char smem[];
    const uint32_t sb = smem_u32(smem);
    const int tid = threadIdx.x, wid = tid >> 5, lane = tid & 31;
    const int m0 = blockIdx.y * BM;
    const int n0 = blockIdx.x * BN;
    const int warp_m = (wid & 3) * 32;
    const int warp_n = (wid >> 2) * 64;

    auto load_stage = [&](int ks, int buf) {
        const int ak = (ks & 7) * 64;
        const int bk = ((ks >> 3) ? 512 : 0) + (ks & 7) * 64;
        const uint32_t abase = sb + buf * STGB;
        const uint32_t bbase = abase + 128u * ROWB;
        #pragma unroll
        for (int t = 0; t < 8; t++) {
            const int idx = tid + t * 256;
            if (idx < 1024) {           // A: 128 rows x 8 chunks
                const int r = idx >> 3, c = (idx & 7) * 8;
                cp16(abase + r * ROWB + c * 2, gA + (size_t)(m0 + r) * 512 + ak + c);
            } else {                    // B: 128 rows x 8 chunks
                const int j = idx - 1024;
                const int r = j >> 3, c = (j & 7) * 8;
                cp16(bbase + r * ROWB + c * 2, gB + (size_t)(n0 + r) * 1024 + bk + c);
            }
        }
    };

    const int NK = 16;
    load_stage(0, 0); CP_COMMIT();
    load_stage(1, 1); CP_COMMIT();

    float acc[2][8][4] = {};
    const int a_row = warp_m + (lane & 15);
    const int a_col = (lane >> 4) * 8;
    const int b_row = warp_n + (lane & 7) + ((lane >> 4) << 3);
    const int b_col = ((lane >> 3) & 1) * 8;

    for (int ks = 0; ks < NK; ks++) {
        CP_WAIT1();
        __syncthreads();
        const int pf = ks + NSTG - 1;
        if (pf < NK) load_stage(pf, pf % NSTG);
        CP_COMMIT();
        const uint32_t abase = sb + (ks % NSTG) * STGB;
        const uint32_t bbase = abase + 128u * ROWB;
        #pragma unroll
        for (int kk = 0; kk < 4; kk++) {
            uint32_t af[2][4], bfr[4][4];
            #pragma unroll
            for (int im = 0; im < 2; im++)
                ldm4(af[im][0], af[im][1], af[im][2], af[im][3],
                     abase + (a_row + im * 16) * ROWB + (kk * 16 + a_col) * 2);
            #pragma unroll
            for (int jn = 0; jn < 4; jn++)
                ldm4(bfr[jn][0], bfr[jn][1], bfr[jn][2], bfr[jn][3],
                     bbase + (b_row + jn * 16) * ROWB + (kk * 16 + b_col) * 2);
            #pragma unroll
            for (int jn = 0; jn < 4; jn++)
                #pragma unroll
                for (int im = 0; im < 2; im++) {
                    mma16816h(acc[im][jn * 2 + 0], af[im], bfr[jn][0], bfr[jn][1]);
                    mma16816h(acc[im][jn * 2 + 1], af[im], bfr[jn][2], bfr[jn][3]);
                }
        }
    }

    const int mb = m0 + warp_m + (lane >> 2);
    #pragma unroll
    for (int im = 0; im < 2; im++) {
        #pragma unroll
        for (int j = 0; j < 8; j++) {
            const int col = n0 + warp_n + j * 8 + (lane & 3) * 2;
            #pragma unroll
            for (int half = 0; half < 2; half++) {
                const int m = mb + im * 16 + half * 8;
                float v0 = acc[im][j][half * 2 + 0] + bias[col];
                float v1 = acc[im][j][half * 2 + 1] + bias[col + 1];
                if (MODE == 0) {
                    const int sct = col >> 9, h = (col >> 6) & 7, d = col & 63;
                    const int bi = m >> 8, nt = m & 255;
                    if (sct == 2) {
                        float2* dp = (float2*)(g_v +
                            (((size_t)(bi * NH + h) * NT + nt) * HDIM + d));
                        *dp = make_float2(v0, v1);
                    } else if (sct == 0) {
                        v0 *= 0.125f; v1 *= 0.125f;
                        __half2 t; t.x = __float2half_rn(v0); t.y = __float2half_rn(v1);
                        *(__half2*)(g_qh + ((size_t)(bi * NH + h) * NT + nt) * 64 + d) = t;
                    } else {
                        __half h0, l0, h1, l1;
                        split1h(v0, h0, l0); split1h(v1, h1, l1);
                        __half* base = g_kes + ((size_t)(bi * NH + h) * NT + nt) * 128 + d;
                        __half2 th, tl; th.x = h0; th.y = h1; tl.x = l0; tl.y = l1;
                        *(__half2*)(base)      = th;
                        *(__half2*)(base + 64) = tl;
                    }
                } else {
                    *(float2*)(outp + (size_t)m * MODEL + col) = make_float2(v0, v1);
                }
            }
        }
    }
}

// ---------------- s_mma: S = q(fp16) @ k_ext^T, load-once, 2 terms ----------
#define SAROW 144u                        // 64 fp16 + pad
#define SBROW 272u                        // 128 fp16 + pad
#define SSMEM (128u * SAROW + 128u * SBROW)   // 53248

__global__ __launch_bounds__(256, 2) void s_mma()
{
    extern __shared__ char smem[];
    const uint32_t sb = smem_u32(smem);
    const int tid = threadIdx.x, wid = tid >> 5, lane = tid & 31;
    const int bh = blockIdx.y;
    const int m0 = (blockIdx.x >> 1) * 128;
    const int n0 = (blockIdx.x & 1) * 128;
    const __half* gA = g_qh  + (size_t)bh * NT * 64;
    const __half* gB = g_kes + (size_t)bh * NT * 128;
    const int warp_m = (wid & 3) * 32;
    const int warp_n = (wid >> 2) * 64;
    const uint32_t abase = sb;
    const uint32_t bbase = sb + 128u * SAROW;

    #pragma unroll
    for (int t = 0; t < 12; t++) {
        const int idx = tid + t * 256;
        if (idx < 1024) {
            const int r = idx >> 3, c = (idx & 7) * 8;
            cp16(abase + r * SAROW + c * 2, gA + (size_t)(m0 + r) * 64 + c);
        } else {
            const int j = idx - 1024;
            const int r = j >> 4, cc = j & 15;
            cp16(bbase + r * SBROW + cc * 16, gB + (size_t)(n0 + r) * 128 + cc * 8);
        }
    }
    CP_COMMIT();
    CP_WAIT0();
    __syncthreads();

    float acc[2][8][4] = {};
    const int a_row = warp_m + (lane & 15);
    const int a_col = (lane >> 4) * 8;
    const int b_row = warp_n + (lane & 7) + ((lane >> 4) << 3);
    const int b_col = ((lane >> 3) & 1) * 8;

    #pragma unroll
    for (int kk = 0; kk < 4; kk++) {
        uint32_t af[2][4];
        #pragma unroll
        for (int im = 0; im < 2; im++)
            ldm4(af[im][0], af[im][1], af[im][2], af[im][3],
                 abase + (a_row + im * 16) * SAROW + (kk * 16 + a_col) * 2);
        #pragma unroll
        for (int term = 0; term < 2; term++) {
            const int bo = term * 64;
            uint32_t bfr[4][4];
            #pragma unroll
            for (int jn = 0; jn < 4; jn++)
                ldm4(bfr[jn][0], bfr[jn][1], bfr[jn][2], bfr[jn][3],
                     bbase + (b_row + jn * 16) * SBROW + (bo + kk * 16 + b_col) * 2);
            #pragma unroll
            for (int jn = 0; jn < 4; jn++)
                #pragma unroll
                for (int im = 0; im < 2; im++) {
                    mma16816h(acc[im][jn * 2 + 0], af[im], bfr[jn][0], bfr[jn][1]);
                    mma16816h(acc[im][jn * 2 + 1], af[im], bfr[jn][2], bfr[jn][3]);
                }
        }
    }

    float* Sp = g_S + (size_t)bh * NT * NT;
    const int mb = m0 + warp_m + (lane >> 2);
    #pragma unroll
    for (int im = 0; im < 2; im++) {
        #pragma unroll
        for (int j = 0; j < 8; j++) {
            const int col = n0 + warp_n + j * 8 + (lane & 3) * 2;
            #pragma unroll
            for (int half = 0; half < 2; half++) {
                const int m = mb + im * 16 + half * 8;
                *(float2*)(Sp + (size_t)m * NT + col) =
                    make_float2(acc[im][j][half * 2], acc[im][j][half * 2 + 1]);
            }
        }
    }
}

// ---------------- vt_kernel: transpose + fp16 split V -----------------------
__global__ __launch_bounds__(256) void vt_kernel()
{
    __shared__ float sv[128 * 65];
    const int bh = blockIdx.x, tid = threadIdx.x;
    const float* V = g_v + (size_t)bh * NT * HDIM;
    __half* dst = g_vte + (size_t)bh * 64 * 512;
    for (int pass = 0; pass < 2; pass++) {
        const int kbase = pass * 128;
        for (int i = tid; i < 128 * 64; i += 256) {
            int k2 = i >> 6, n = i & 63;
            sv[k2 * 65 + n] = V[(size_t)(kbase + k2) * 64 + n];
        }
        __syncthreads();
        const int n = tid >> 2, q = tid & 3;
        for (int kk = 0; kk < 32; kk += 2) {
            const int k2 = q * 32 + kk;
            float v0 = sv[k2 * 65 + n], v1 = sv[(k2 + 1) * 65 + n];
            __half h0, l0, h1, l1;
            split1h(v0, h0, l0); split1h(v1, h1, l1);
            __half2 th, tl; th.x = h0; th.y = h1; tl.x = l0; tl.y = l1;
            const int k = kbase + k2;
            *(__half2*)(dst + (size_t)n * 512 + k)       = th;
            *(__half2*)(dst + (size_t)n * 512 + 256 + k) = tl;
        }
        __syncthreads();
    }
}

// ---------------- conv + bias + softmax -> P fp16 ---------------------------
__global__ __launch_bounds__(256) void conv_softmax_kernel(
    const float* __restrict__ pe_w, const float* __restrict__ pe_b,
    const float* __restrict__ rpb)
{
    __shared__ float st[32][NT];
    const int bh = blockIdx.y;
    const int h  = bh & 7;
    const int i0 = blockIdx.x * 32;
    const float* S = g_S + (size_t)bh * NT * NT;
    __half* pe = g_ph + (size_t)bh * NT * NT;
    const int j = threadIdx.x;

    float win[46];
    #pragma unroll
    for (int r = 0; r < 46; r++) {
        const int g = i0 - 7 + r;
        win[r] = (g >= 0 && g < NT) ? S[(size_t)g * NT + j] : 0.f;
    }
    float w[15];
    #pragma unroll
    for (int t = 0; t < 15; t++) w[t] = pe_w[h * 15 + t];
    const float pb = pe_b[h];
    const int rj = j >> 4, cj = j & 15;

    #pragma unroll
    for (int li = 0; li < 32; li++) {
        float conv = 0.f;
        #pragma unroll
        for (int t = 0; t < 15; t++)
            conv = fmaf(win[li + t], w[t], conv);
        const int ii = i0 + li;
        const int ri = ii >> 4, ci = ii & 15;
        const int idx = (ri - rj + 15) * 31 + (ci - cj + 15);
        st[li][j] = win[li + 7] + conv + pb + __ldg(&rpb[idx * 8 + h]);
    }
    __syncthreads();

    const int warp = j >> 5, lane = j & 31;
    #pragma unroll
    for (int rr = 0; rr < 4; rr++) {
        const int li = warp * 4 + rr;
        const int ii = i0 + li;
        float vals[8];
        #pragma unroll
        for (int e = 0; e < 8; e++) vals[e] = st[li][lane + e * 32];
        float mx = vals[0];
        #pragma unroll
        for (int e = 1; e < 8; e++) mx = fmaxf(mx, vals[e]);
        #pragma unroll
        for (int o = 16; o; o >>= 1) mx = fmaxf(mx, __shfl_xor_sync(0xffffffffu, mx, o));
        float sum = 0.f;
        #pragma unroll
        for (int e = 0; e < 8; e++) { vals[e] = __expf(vals[e] - mx); sum += vals[e]; }
        #pragma unroll
        for (int o = 16; o; o >>= 1) sum += __shfl_xor_sync(0xffffffffu, sum, o);
        const float inv = 1.f / sum;
        #pragma unroll
        for (int e = 0; e < 8; e++)
            pe[(size_t)ii * NT + lane + e * 32] = __float2half_rn(vals[e] * inv);
    }
}

// ---------------- av_mma: O = P(fp16) @ V_ext^T, 2 terms, K-chunks of 64 ----
#define AVAROW 144u
#define AV_A  0u
#define AV_BH (256u * AVAROW)             // 36864
#define AV_BL (AV_BH + 64u * AVAROW)      // 46080
#define AV_STG (AV_BL + 64u * AVAROW)     // 55296
#define AVSMEM (2u * AV_STG)              // 110592

__global__ __launch_bounds__(256, 2) void av_mma()
{
    extern __shared__ char smem[];
    const uint32_t sb = smem_u32(smem);
    const int tid = threadIdx.x, wid = tid >> 5, lane = tid & 31;
    const int bh = blockIdx.x;
    const __half* gA = g_ph  + (size_t)bh * NT * NT;
    const __half* gB = g_vte + (size_t)bh * 64 * 512;
    const int warp_m = (wid & 3) * 64;
    const int warp_n = (wid >> 2) * 32;

    auto load_stage = [&](int c, int buf) {
        const uint32_t base = sb + buf * AV_STG;
        const int ck = c * 64;
        #pragma unroll
        for (int t = 0; t < 12; t++) {
            const int idx = tid + t * 256;
            if (idx < 2048) {                     // P: 256 rows x 8 chunks
                const int r = idx >> 3, col = (idx & 7) * 8;
                cp16(base + AV_A + r * AVAROW + col * 2,
                     gA + (size_t)r * 256 + ck + col);
            } else if (idx < 2560) {              // Vh: 64 rows x 8 chunks
                const int i2 = idx - 2048;
                const int r = i2 >> 3, col = (i2 & 7) * 8;
                cp16(base + AV_BH + r * AVAROW + col * 2,
                     gB + (size_t)r * 512 + ck + col);
            } else {                              // Vl
                const int i3 = idx - 2560;
                const int r = i3 >> 3, col = (i3 & 7) * 8;
                cp16(base + AV_BL + r * AVAROW + col * 2,
                     gB + (size_t)r * 512 + 256 + ck + col);
            }
        }
    };

    load_stage(0, 0); CP_COMMIT();

    float acc[4][4][4] = {};
    const int a_row = warp_m + (lane & 15);
    const int a_col = (lane >> 4) * 8;
    const int b_row = warp_n + (lane & 7) + ((lane >> 4) << 3);
    const int b_col = ((lane >> 3) & 1) * 8;

    for (int ks = 0; ks < 4; ks++) {
        if (ks > 0) __syncthreads();
        if (ks + 1 < 4) load_stage(ks + 1, (ks + 1) & 1);
        CP_COMMIT();
        if (ks < 3) CP_WAIT1(); else CP_WAIT0();
        __syncthreads();
        const uint32_t base = sb + (ks & 1) * AV_STG;
        #pragma unroll
        for (int kk = 0; kk < 4; kk++) {
            uint32_t af[4][4];
            #pragma unroll
            for (int im = 0; im < 4; im++)
                ldm4(af[im][0], af[im][1], af[im][2], af[im][3],
                     base + AV_A + (a_row + im * 16) * AVAROW + (kk * 16 + a_col) * 2);
            #pragma unroll
            for (int hv = 0; hv < 2; hv++) {
                const uint32_t bbase = base + (hv ? AV_BL : AV_BH);
                uint32_t bfr[2][4];
                #pragma unroll
                for (int jn = 0; jn < 2; jn++)
                    ldm4(bfr[jn][0], bfr[jn][1], bfr[jn][2], bfr[jn][3],
                         bbase + (b_row + jn * 16) * AVAROW + (kk * 16 + b_col) * 2);
                #pragma unroll
                for (int jn = 0; jn < 2; jn++)
                    #pragma unroll
                    for (int im = 0; im < 4; im++) {
                        mma16816h(acc[im][jn * 2 + 0], af[im], bfr[jn][0], bfr[jn][1]);
                        mma16816h(acc[im][jn * 2 + 1], af[im], bfr[jn][2], bfr[jn][3]);
                    }
            }
        }
    }

    const int bi = bh >> 3, hh = bh & 7;
    #pragma unroll
    for (int im = 0; im < 4; im++) {
        #pragma unroll
        for (int j = 0; j < 4; j++) {
            const int col = warp_n + j * 8 + (lane & 3) * 2;   // 0..63
            #pragma unroll
            for (int half = 0; half < 2; half++) {
                const int m = warp_m + im * 16 + (lane >> 2) + half * 8;
                __half2 t;
                t.x = __float2half_rn(acc[im][j][half * 2 + 0]);
                t.y = __float2half_rn(acc[im][j][half * 2 + 1]);
                *(__half2*)(g_oh16 + (size_t)(bi * NT + m) * MODEL + hh * 64 + col) = t;
            }
        }
    }
}

// ---------------------------------------------------------------------------
extern "C" void kernel_launch(void* const* d_in, const int* in_sizes, int n_in,
                              void* d_out, int out_size)
{
    (void)in_sizes; (void)n_in; (void)out_size;
    const float* x      = (const float*)d_in[0];
    const float* qkv_w  = (const float*)d_in[1];
    const float* qkv_b  = (const float*)d_in[2];
    const float* pe_w   = (const float*)d_in[3];
    const float* pe_b   = (const float*)d_in[4];
    const float* rpb    = (const float*)d_in[5];
    const float* proj_w = (const float*)d_in[6];
    const float* proj_b = (const float*)d_in[7];
    float* out = (float*)d_out;

    static bool attr_done = false;
    if (!attr_done) {
        cudaFuncSetAttribute(gemm_mma<0>, cudaFuncAttributeMaxDynamicSharedMemorySize, GSMEM);
        cudaFuncSetAttribute(gemm_mma<1>, cudaFuncAttributeMaxDynamicSharedMemorySize, GSMEM);
        cudaFuncSetAttribute(s_mma, cudaFuncAttributeMaxDynamicSharedMemorySize, SSMEM);
        cudaFuncSetAttribute(av_mma, cudaFuncAttributeMaxDynamicSharedMemorySize, AVSMEM);
        attr_done = true;
    }

    __half *xh, *qws, *pws, *oh16;
    cudaGetSymbolAddress((void**)&xh,   g_xh);
    cudaGetSymbolAddress((void**)&qws,  g_qwse);
    cudaGetSymbolAddress((void**)&pws,  g_pwse);
    cudaGetSymbolAddress((void**)&oh16, g_oh16);

    rnd_x_kernel<<<(MTOT * MODEL / 2 + 255) / 256, 256>>>(x, xh, MTOT * MODEL / 2);
    wsplit_kernel<<<(QKVN * MODEL / 2 + 255) / 256, 256>>>(qkv_w, qws, QKVN * MODEL / 2);
    wsplit_kernel<<<(MODEL * MODEL / 2 + 255) / 256, 256>>>(proj_w, pws, MODEL * MODEL / 2);

    gemm_mma<0><<<dim3(QKVN / BN, MTOT / BM), 256, GSMEM>>>(xh, qws, qkv_b, nullptr);

    vt_kernel<<<NBH, 256>>>();
    s_mma<<<dim3(4, NBH), 256, SSMEM>>>();
    conv_softmax_kernel<<<dim3(8, NBH), 256>>>(pe_w, pe_b, rpb);
    av_mma<<<NBH, 256, AVSMEM>>>();

    gemm_mma<1><<<dim3(MODEL / BN, MTOT / BM), 256, GSMEM>>>(oh16, pws, proj_b, out);
}